// round 14
// baseline (speedup 1.0000x reference)
#include <cuda_runtime.h>

// Problem constants
#define T_STEPS 512
#define NBATCH  512
#define IN_DIM  64
#define H       100

// Exact (unpadded) concat lengths:
// L1 input [x(64) | h1(100)]  -> 164 floats: 8 k-chunks of 20 (10 u64) + 4 tail floats (lanes 0-3)
// L2 input [h1(100) | h2(100)]-> 200 floats: 8 k-chunks of 24 (12 u64) + 8 tail floats (one per lane)
#define L1_LEN  164
#define L2_LEN  200

#define ROWS     4      // batch rows per CTA
#define NCTA     128    // 128 * 4 = 512 rows
#define NTHREADS 256    // 8 warps: wid 0-3 L1, wid 4-7 L2.  SMSP s = {wid s (L1), wid s+4 (L2)}
                        // CPT per warp: L1 (7,6,6,6), L2 wid5=7 others 6 -> per-SMSP FFMA2 max 576.

typedef unsigned long long ull;

__device__ float g_W1T[H * L1_LEN];   // [col][k], transposed + concatenated, NO padding
__device__ float g_W2T[H * L2_LEN];

__global__ void prep_kernel(const float* __restrict__ W1x, const float* __restrict__ W1h,
                            const float* __restrict__ W2x, const float* __restrict__ W2h) {
    int idx = blockIdx.x * blockDim.x + threadIdx.x;
    const int n1 = H * L1_LEN;
    if (idx < n1) {
        int j = idx / L1_LEN, k = idx % L1_LEN;
        g_W1T[idx] = (k < IN_DIM) ? W1x[k * H + j] : W1h[(k - IN_DIM) * H + j];
    } else {
        int i2 = idx - n1;
        if (i2 < H * L2_LEN) {
            int j = i2 / L2_LEN, k = i2 % L2_LEN;
            g_W2T[i2] = (k < H) ? W2x[k * H + j] : W2h[(k - H) * H + j];
        }
    }
}

// Accurate fast tanh: 1 - 2/(exp(2x)+1).  __expf = MUFU.EX2 path, rel err ~1e-6.
__device__ __forceinline__ float fast_tanh(float x) {
    float e = __expf(2.0f * x);
    return 1.0f - __fdividef(2.0f, e + 1.0f);
}

// Packed fp32 FMA (sm_103a FFMA2): acc = a*b + acc, two k-lanes at once.
__device__ __forceinline__ void ffma2(ull& acc, ull a, ull b) {
    asm("fma.rn.f32x2 %0, %1, %2, %0;" : "+l"(acc) : "l"(a), "l"(b));
}

__device__ __forceinline__ float hadd2(ull a) {
    float lo, hi;
    asm("mov.b64 {%0, %1}, %2;" : "=f"(lo), "=f"(hi) : "l"(a));
    return lo + hi;
}

// Reduce-scatter 16 values over the 8 k-split lanes: lane s ends with
// o0 = full sum of v[s], o1 = full sum of v[8+s].
// v index layout: v = sel*8 + colLow*2 + r2.
__device__ __forceinline__ void reduce16(const float (&v)[16], int s, float& o0, float& o1) {
    const int c2 = (s & 4) ? 4 : 0, c1 = (s & 2) ? 2 : 0, c0 = s & 1;
    float a8[8];
    #pragma unroll
    for (int j = 0; j < 8; ++j) {               // j = (b3 b1 b0)
        int lo = j & 3, hi = (j >> 2) << 3;
        float keep = v[hi | c2 | lo];
        float send = v[hi | (4 - c2 - ((c2 >> 2) * 0)) - ((c2) ? 4 : 0) | 0];  // placeholder, fixed below
        send = v[hi | (c2 ^ 4) | lo];
        a8[j] = keep + __shfl_xor_sync(0xffffffffu, send, 4);
    }
    float a4[4];
    #pragma unroll
    for (int j = 0; j < 4; ++j) {               // j = (b3 b0)
        int lo = j & 1, hi = (j >> 1) << 2;
        float keep = a8[hi | c1 | lo];
        float send = a8[hi | (c1 ^ 2) | lo];
        a4[j] = keep + __shfl_xor_sync(0xffffffffu, send, 2);
    }
    #pragma unroll
    for (int j = 0; j < 2; ++j) {               // j = b3
        int hi = j << 1;
        float keep = a4[hi | c0];
        float send = a4[hi | (c0 ^ 1)];
        float r = keep + __shfl_xor_sync(0xffffffffu, send, 1);
        if (j == 0) o0 = r; else o1 = r;
    }
}

// One warp's full time-loop. LAYER = 1 or 2.  CPT columns per thread.
// Executes exactly (T_STEPS+1) __syncthreads, matching all other warps.
template<int CPT, int LAYER>
__device__ __forceinline__ void run_loop(
    float* __restrict__ s1, float* __restrict__ s2,     // flattened [2][ROWS][LEN]
    const float4* __restrict__ xg4,
    const float* __restrict__ bias,
    float* __restrict__ out, int b0,
    int colBase, int lane, bool isPre, int pre_r, int pre_d)
{
    constexpr int NP     = (LAYER == 1) ? 10 : 12;        // u64 per k-chunk
    constexpr int ROWLEN = (LAYER == 1) ? L1_LEN : L2_LEN;
    constexpr int TAILB  = (LAYER == 1) ? 160 : 192;
    const int g = lane >> 3, s = lane & 7;
    const bool tailAct = (LAYER == 1) ? (s < 4) : true;
    const float* __restrict__ W = (LAYER == 1) ? g_W1T : g_W2T;

    // Weights: CPT columns x (NP u64 + 1 tail float)
    ull   w[CPT][NP];
    float wt[CPT];
    #pragma unroll
    for (int c = 0; c < CPT; ++c) {
        int col = colBase + g * CPT + c;
        const ull* p = (const ull*)(W + col * ROWLEN) + s * NP;
        #pragma unroll
        for (int i = 0; i < NP; ++i) w[c][i] = p[i];
        wt[c] = tailAct ? W[col * ROWLEN + TAILB + s] : 0.0f;
    }

    // Outputs of reduce16 on this lane: cols ocol0 / ocol1 of row rb+(s&1).
    const int  ocol0  = colBase + g * CPT + (s >> 1);
    const int  ocol1  = colBase + g * CPT + 4 + (s >> 1);
    const bool valid1 = (4 + (s >> 1)) < CPT;
    const float bias0 = bias[ocol0];
    const float bias1 = bias[valid1 ? ocol1 : ocol0];

    for (int p = 0; p <= T_STEPS; ++p) {
        const int pb = p & 1;

        float4 xpre;
        const bool doPre = isPre && (p + 1 < T_STEPS);
        if (doPre)
            xpre = xg4[(b0 + pre_r) * (T_STEPS * (IN_DIM / 4)) + (p + 1) * (IN_DIM / 4) + pre_d];

        const bool active = (LAYER == 1) ? (p < T_STEPS) : (p >= 1);
        if (active) {
            #pragma unroll
            for (int rb = 0; rb < ROWS; rb += 2) {
                float v16[16];
                #pragma unroll
                for (int i = 0; i < 16; ++i) v16[i] = 0.0f;

                #pragma unroll
                for (int r2 = 0; r2 < 2; ++r2) {
                    const float* row = (LAYER == 1)
                        ? (s1 + (pb * ROWS + rb + r2) * L1_LEN)
                        : (s2 + (pb * ROWS + rb + r2) * L2_LEN);
                    const ull* vin = (const ull*)row + s * NP;
                    float vt = tailAct ? row[TAILB + s] : 0.0f;
                    ull acc[CPT];
                    #pragma unroll
                    for (int c = 0; c < CPT; ++c) acc[c] = 0ull;
                    #pragma unroll
                    for (int i = 0; i < NP; ++i) {
                        ull vv = vin[i];
                        #pragma unroll
                        for (int c = 0; c < CPT; ++c) ffma2(acc[c], w[c][i], vv);
                    }
                    #pragma unroll
                    for (int c = 0; c < CPT; ++c) {
                        float Ac = fmaf(wt[c], vt, hadd2(acc[c]));
                        int vidx = (c < 4) ? (c * 2 + r2) : (8 + (c - 4) * 2 + r2);
                        v16[vidx] = Ac;
                    }
                }

                float o0, o1;
                reduce16(v16, s, o0, o1);
                float h0 = fast_tanh(o0 + bias0);
                float h1v = fast_tanh(o1 + bias1);
                const int r = rb + (s & 1);
                const int nb = pb ^ 1;
                if (LAYER == 1) {
                    s1[(nb * ROWS + r) * L1_LEN + IN_DIM + ocol0] = h0;
                    s2[(nb * ROWS + r) * L2_LEN + ocol0]          = h0;
                    if (valid1) {
                        s1[(nb * ROWS + r) * L1_LEN + IN_DIM + ocol1] = h1v;
                        s2[(nb * ROWS + r) * L2_LEN + ocol1]          = h1v;
                    }
                    if (p == T_STEPS - 1) {
                        out[NBATCH + (b0 + r) * H + ocol0] = h0;              // h1_T
                        if (valid1) out[NBATCH + (b0 + r) * H + ocol1] = h1v;
                    }
                } else {
                    s2[(nb * ROWS + r) * L2_LEN + H + ocol0] = h0;
                    if (valid1) s2[(nb * ROWS + r) * L2_LEN + H + ocol1] = h1v;
                    if (p == T_STEPS) {
                        out[NBATCH + NBATCH * H + (b0 + r) * H + ocol0] = h0; // h2_T
                        if (valid1) out[NBATCH + NBATCH * H + (b0 + r) * H + ocol1] = h1v;
                    }
                }
            }
        }

        if (doPre) {
            float4* dst = (float4*)(s1 + ((pb ^ 1) * ROWS + pre_r) * L1_LEN);
            dst[pre_d] = xpre;
        }
        __syncthreads();
    }
}

__global__ void __launch_bounds__(NTHREADS, 1)
rnn_kernel(const float* __restrict__ x,
           const float* __restrict__ b1, const float* __restrict__ b2,
           const float* __restrict__ Wo, const float* __restrict__ bo,
           float* __restrict__ out) {
    __shared__ __align__(16) float s_in1[2][ROWS][L1_LEN];
    __shared__ __align__(16) float s_in2[2][ROWS][L2_LEN];
    float* s1 = &s_in1[0][0][0];
    float* s2 = &s_in2[0][0][0];

    const int t   = threadIdx.x;
    const int wid = t >> 5;
    const int lane = t & 31;
    const int b0  = blockIdx.x * ROWS;
    const float4* __restrict__ xg4 = (const float4*)x;

    for (int i = t; i < 2 * ROWS * L1_LEN; i += NTHREADS) s1[i] = 0.0f;
    for (int i = t; i < 2 * ROWS * L2_LEN; i += NTHREADS) s2[i] = 0.0f;
    __syncthreads();

    // Stage x(0) into buffer 0 (threads 0-63 = L1 warps 0-1).
    const int pre_r = (t >> 4) & 3, pre_d = t & 15;
    if (t < 64)
        ((float4*)(s1 + pre_r * L1_LEN))[pre_d] =
            xg4[(b0 + pre_r) * (T_STEPS * (IN_DIM / 4)) + pre_d];
    __syncthreads();

    const bool isPre = (t < 64);

    // Warp dispatch: L1 CPT (7,6,6,6) on wid 0-3; L2 CPT: wid5=7, wid 4/6/7=6.
    // Column bases chosen so each layer covers cols 0-99 exactly (zero dummies).
    if (wid == 0)
        run_loop<7, 1>(s1, s2, xg4, b1, out, b0, 0,                lane, isPre, pre_r, pre_d);
    else if (wid < 4)
        run_loop<6, 1>(s1, s2, xg4, b1, out, b0, 28 + (wid - 1) * 24, lane, isPre, pre_r, pre_d);
    else if (wid == 5)
        run_loop<7, 2>(s1, s2, xg4, b2, out, b0, 0,                lane, false, 0, 0);
    else
        run_loop<6, 2>(s1, s2, xg4, b2, out, b0,
                       (wid == 4) ? 28 : 28 + (wid - 5) * 24,      lane, false, 0, 0);

    // out = h2_T @ Wo + bo.  h2(T-1) written at phase 512 (pb=0) into buffer 1,
    // ordered by the loops' final __syncthreads.
    if (t < ROWS) {
        float acc = bo[0];
        #pragma unroll 4
        for (int k = 0; k < H; ++k)
            acc = fmaf(s2[(1 * ROWS + t) * L2_LEN + H + k], Wo[k], acc);
        out[b0 + t] = acc;
    }
}

extern "C" void kernel_launch(void* const* d_in, const int* in_sizes, int n_in,
                              void* d_out, int out_size) {
    const float* x   = (const float*)d_in[0];
    const float* W1x = (const float*)d_in[1];
    const float* W1h = (const float*)d_in[2];
    const float* b1  = (const float*)d_in[3];
    const float* W2x = (const float*)d_in[4];
    const float* W2h = (const float*)d_in[5];
    const float* b2  = (const float*)d_in[6];
    const float* Wo  = (const float*)d_in[7];
    const float* bo  = (const float*)d_in[8];
    float* out = (float*)d_out;

    // Build transposed weight images (36400 elements, no padding).
    prep_kernel<<<143, 256>>>(W1x, W1h, W2x, W2h);

    // Persistent batch-partitioned RNN: 128 CTAs x 4 rows, no inter-CTA sync.
    rnn_kernel<<<NCTA, NTHREADS>>>(x, b1, b2, Wo, bo, out);
}